// round 12
// baseline (speedup 1.0000x reference)
#include <cuda_runtime.h>
#include <stdint.h>

// core0: (1,50,8,16) A[v0][e0][r1] ; core1: (16,50,4,16) B[r1][v1][e1][r2]
// core2: (16,80,4,1) C[r2][v2][e2] ; indices: 8192 of vocab 200000=(50,50,80)
// out[n][e0*16+e1*4+e2] fp32

#define NV1 50
#define NV2 80
#define RANK 16
#define NIDX 8192
#define NPAIRS (NV1 * NV2)      // 4000

// TRANSPOSED intermediate: H_T[p][e12][r1], r1 contiguous. 4 MB, L2-resident.
__device__ float g_HT[NPAIRS * 16 * RANK];

// ---------------------------------------------------------------------------
// Kernel 1: block = 8 pairs sharing v1 (80 % 8 == 0). Each warp computes its
// 16x16 tile H[r1][e12], parks it in smem, then writes it TRANSPOSED
// (H_T[e12][r1]) with coalesced STG.128.
// ---------------------------------------------------------------------------
__global__ __launch_bounds__(256) void tt_build_HT(
    const float* __restrict__ core1,
    const float* __restrict__ core2)
{
    __shared__ __align__(16) float  sB[16 * 68];      // B[:,v1] padded chunks
    __shared__ __align__(16) float4 sc[8][16];        // per-warp C slice
    __shared__ float sH[8][16 * 17];                  // per-warp tile, padded

    const int tid  = threadIdx.x;
    const int w    = tid >> 5;
    const int lane = tid & 31;
    const int pair0 = blockIdx.x * 8;
    const int v1    = pair0 / NV2;
    const int v2    = (pair0 - v1 * NV2) + w;

    {
        const int r1 = tid >> 4;
        const int c4 = tid & 15;
        const float4 b = __ldg((const float4*)(core1 + ((size_t)r1 * NV1 + v1) * 64) + c4);
        *(float4*)&sB[r1 * 68 + c4 * 4] = b;
    }
    if (lane < RANK)
        sc[w][lane] = __ldg((const float4*)(core2 + ((size_t)lane * NV2 + v2) * 4));
    __syncthreads();

    // Compute tile -> sH[w][r1*17 + e12]
#pragma unroll
    for (int pass = 0; pass < 2; ++pass) {
        const int j  = lane + 32 * pass;              // 0..63
        const int r1 = j >> 2;
        const int e1 = j & 3;
        const float* bp = &sB[r1 * 68 + e1 * 16];
        float4 acc = make_float4(0.f, 0.f, 0.f, 0.f);
#pragma unroll
        for (int r2 = 0; r2 < RANK; ++r2) {
            const float bbv = bp[r2];
            const float4 c4 = sc[w][r2];
            acc.x = fmaf(bbv, c4.x, acc.x);
            acc.y = fmaf(bbv, c4.y, acc.y);
            acc.z = fmaf(bbv, c4.z, acc.z);
            acc.w = fmaf(bbv, c4.w, acc.w);
        }
        float* dst = &sH[w][r1 * 17 + e1 * 4];
        dst[0] = acc.x; dst[1] = acc.y; dst[2] = acc.z; dst[3] = acc.w;
    }
    __syncwarp();

    // Transposed write-out: float4 chunk o of H_T = (e12 = o>>2, r1 = (o&3)*4..+3)
    float* houtT = g_HT + (size_t)(v1 * NV2 + v2) * 256;
#pragma unroll
    for (int s = 0; s < 2; ++s) {
        const int o   = lane + 32 * s;                // 0..63
        const int e12 = o >> 2;
        const int rq  = o & 3;
        float4 v;
        v.x = sH[w][(rq * 4 + 0) * 17 + e12];
        v.y = sH[w][(rq * 4 + 1) * 17 + e12];
        v.z = sH[w][(rq * 4 + 2) * 17 + e12];
        v.w = sH[w][(rq * 4 + 3) * 17 + e12];
        ((float4*)houtT)[o] = v;                      // coalesced STG.128
    }
}

// ---------------------------------------------------------------------------
// Kernel 2: ONE THREAD PER OUTPUT ELEMENT. 128 threads per index; thread t:
//   e0 = t>>4 (A row, 16-thread broadcast), e12 = t&15 (H_T row, contiguous).
//   out[n][t] = dot16(A[v0][e0][:], H_T[p][e12][:])
// No smem, no shuffles: all operands land in the consuming lane.
// Block = 256 threads = 2 indices.
// ---------------------------------------------------------------------------
__global__ __launch_bounds__(256) void tt_gather(
    const void* __restrict__ idx_raw,
    const float* __restrict__ core0,
    float* __restrict__ out)
{
    const int tid  = threadIdx.x;
    const int lane = tid & 31;
    const int n    = blockIdx.x * 2 + (tid >> 7);     // index id
    const int t    = tid & 127;                       // output column

    // dtype sniff: int64 vs int32 (values < 2e5 -> int64 high words all zero)
    const int* i32 = (const int*)idx_raw;
    const bool is64 = __all_sync(0xffffffffu, i32[2 * lane + 1] == 0);

    int iv;
    if (is64) iv = (int)((const long long*)idx_raw)[n];   // group-uniform
    else      iv = i32[n];

    const int v0 = iv / NPAIRS;
    const int p  = iv - v0 * NPAIRS;

    const float4* Ap = (const float4*)(core0 + ((size_t)v0 * 8 + (t >> 4)) * RANK);
    const float4* Hp = (const float4*)(g_HT + (size_t)p * 256 + (size_t)(t & 15) * RANK);

    // 8 independent LDG.128 up front (A instr: 2 distinct addr/warp = 1 wf;
    // H instr: 16 distinct addr/warp = 2 wf).
    const float4 a0 = __ldg(&Ap[0]);
    const float4 a1 = __ldg(&Ap[1]);
    const float4 a2 = __ldg(&Ap[2]);
    const float4 a3 = __ldg(&Ap[3]);
    const float4 h0 = __ldg(&Hp[0]);
    const float4 h1 = __ldg(&Hp[1]);
    const float4 h2 = __ldg(&Hp[2]);
    const float4 h3 = __ldg(&Hp[3]);

    // 4 partial chains for ILP.
    float s0 = a0.x * h0.x;
    float s1 = a0.y * h0.y;
    float s2 = a0.z * h0.z;
    float s3 = a0.w * h0.w;
    s0 = fmaf(a1.x, h1.x, s0);
    s1 = fmaf(a1.y, h1.y, s1);
    s2 = fmaf(a1.z, h1.z, s2);
    s3 = fmaf(a1.w, h1.w, s3);
    s0 = fmaf(a2.x, h2.x, s0);
    s1 = fmaf(a2.y, h2.y, s1);
    s2 = fmaf(a2.z, h2.z, s2);
    s3 = fmaf(a2.w, h2.w, s3);
    s0 = fmaf(a3.x, h3.x, s0);
    s1 = fmaf(a3.y, h3.y, s1);
    s2 = fmaf(a3.z, h3.z, s2);
    s3 = fmaf(a3.w, h3.w, s3);

    out[(size_t)n * 128 + t] = (s0 + s1) + (s2 + s3);
}

// Inputs (metadata order): indices, core0, core1, core2
extern "C" void kernel_launch(void* const* d_in, const int* in_sizes, int n_in,
                              void* d_out, int out_size)
{
    const void*  indices = d_in[0];
    const float* core0   = (const float*)d_in[1];
    const float* core1   = (const float*)d_in[2];
    const float* core2   = (const float*)d_in[3];
    float* out = (float*)d_out;

    tt_build_HT<<<NPAIRS / 8, 256>>>(core1, core2);
    tt_gather<<<NIDX / 2, 256>>>(indices, core0, out);
}

// round 13
// speedup vs baseline: 1.6099x; 1.6099x over previous
#include <cuda_runtime.h>
#include <stdint.h>

// core0: (1,50,8,16) A[v0][e0][r1] ; core1: (16,50,4,16) B[r1][v1][e1][r2]
// core2: (16,80,4,1) C[r2][v2][e2] ; indices: 8192 of vocab 200000=(50,50,80)
// out[n][e0*16+e1*4+e2] fp32

#define NV1 50
#define NV2 80
#define RANK 16
#define NIDX 8192
#define NPAIRS (NV1 * NV2)      // 4000
#define IPW 4                   // indices per warp
#define GWARPS (NIDX / IPW)     // 2048
#define GBLOCKS (GWARPS / 8)    // 256

// H[(v1*80+v2)][r1][e1*4+e2]: 4 MB, L2-resident
__device__ float g_H[NPAIRS * RANK * 16];

__device__ __forceinline__ void cpasync16(uint32_t dst, const void* src) {
    asm volatile("cp.async.cg.shared.global [%0], [%1], 16;" :: "r"(dst), "l"(src) : "memory");
}
template <int N>
__device__ __forceinline__ void cpwait() {
    asm volatile("cp.async.wait_group %0;" :: "n"(N) : "memory");
}

// ---------------------------------------------------------------------------
// Kernel 1: block = 8 pairs sharing v1 (80 % 8 == 0). Unchanged from R11.
// ---------------------------------------------------------------------------
__global__ __launch_bounds__(256) void tt_build_H(
    const float* __restrict__ core1,
    const float* __restrict__ core2)
{
    __shared__ __align__(16) float  sB[16 * 68];
    __shared__ __align__(16) float4 sc[8][16];

    const int tid  = threadIdx.x;
    const int w    = tid >> 5;
    const int lane = tid & 31;
    const int pair0 = blockIdx.x * 8;
    const int v1    = pair0 / NV2;
    const int v2    = (pair0 - v1 * NV2) + w;

    {
        const int r1 = tid >> 4;
        const int c4 = tid & 15;
        const float4 b = __ldg((const float4*)(core1 + ((size_t)r1 * NV1 + v1) * 64) + c4);
        *(float4*)&sB[r1 * 68 + c4 * 4] = b;
    }
    if (lane < RANK)
        sc[w][lane] = __ldg((const float4*)(core2 + ((size_t)lane * NV2 + v2) * 4));
    __syncthreads();

    float* hout = g_H + (size_t)(v1 * NV2 + v2) * (RANK * 16);

#pragma unroll
    for (int pass = 0; pass < 2; ++pass) {
        const int j  = lane + 32 * pass;
        const int r1 = j >> 2;
        const int e1 = j & 3;
        const float* bp = &sB[r1 * 68 + e1 * 16];
        float4 acc = make_float4(0.f, 0.f, 0.f, 0.f);
#pragma unroll
        for (int r2 = 0; r2 < RANK; ++r2) {
            const float bbv = bp[r2];
            const float4 c4 = sc[w][r2];
            acc.x = fmaf(bbv, c4.x, acc.x);
            acc.y = fmaf(bbv, c4.y, acc.y);
            acc.z = fmaf(bbv, c4.z, acc.z);
            acc.w = fmaf(bbv, c4.w, acc.w);
        }
        ((float4*)hout)[j] = acc;
    }
}

// ---------------------------------------------------------------------------
// Kernel 2: warp = 4 indices, 3-stage cp.async pipeline.
// Stage layout (float4): [0..31]=A tile, [32..95]=H tile.
// Lane l: e0=l>>2, q=l&3 owns out[l*4 .. l*4+3] of each row.
// ---------------------------------------------------------------------------
__global__ __launch_bounds__(256) void tt_gather(
    const void* __restrict__ idx_raw,
    const float* __restrict__ core0,
    float* __restrict__ out)
{
    __shared__ __align__(16) float4 sh[8][3][96];   // 36 KB

    const int w    = threadIdx.x >> 5;
    const int lane = threadIdx.x & 31;
    const int base = (blockIdx.x * 8 + w) * IPW;    // first index of this warp

    // dtype sniff: int64 vs int32 (values < 2e5 -> int64 high words all zero)
    const int* i32 = (const int*)idx_raw;
    const bool is64 = __all_sync(0xffffffffu, i32[2 * lane + 1] == 0);
    const long long* i64 = (const long long*)idx_raw;

    // Decompose all 4 indices up front (warp-uniform scalar loads, L2-hot).
    int v0[IPW], p[IPW];
#pragma unroll
    for (int i = 0; i < IPW; ++i) {
        const int iv = is64 ? (int)i64[base + i] : i32[base + i];
        v0[i] = iv / NPAIRS;
        p[i]  = iv - v0[i] * NPAIRS;
    }

    const int e0 = lane >> 2;
    const int q  = lane & 3;

    // Issue one stage's 3 copies (1 commit group).
    auto issue = [&](int i, int s) {
        const float4* At = (const float4*)core0 + (size_t)v0[i] * 32;
        const float4* Ht = (const float4*)g_H   + (size_t)p[i]  * 64;
        const uint32_t sb = (uint32_t)__cvta_generic_to_shared(&sh[w][s][0]);
        cpasync16(sb + lane * 16,        At + lane);
        cpasync16(sb + (32 + lane) * 16, Ht + lane);
        cpasync16(sb + (64 + lane) * 16, Ht + lane + 32);
        asm volatile("cp.async.commit_group;" ::: "memory");
    };

    // Prologue: stages 0 and 1 in flight.
    issue(0, 0);
    issue(1, 1);

#pragma unroll
    for (int i = 0; i < IPW; ++i) {
        // Wait for stage i: pending groups allowed = groups issued - (i+1).
        if (i < IPW - 2)      cpwait<1>();
        else if (i == IPW - 2) cpwait<1>();
        else                   cpwait<0>();
        __syncwarp();

        const int s = i % 3;

        float a[RANK];
#pragma unroll
        for (int k = 0; k < 4; ++k) {
            const float4 t4 = sh[w][s][e0 * 4 + k];
            a[4 * k + 0] = t4.x; a[4 * k + 1] = t4.y;
            a[4 * k + 2] = t4.z; a[4 * k + 3] = t4.w;
        }

        float4 acc = make_float4(0.f, 0.f, 0.f, 0.f);
#pragma unroll
        for (int r1 = 0; r1 < RANK; ++r1) {
            const float4 h = sh[w][s][32 + r1 * 4 + q];
            acc.x = fmaf(a[r1], h.x, acc.x);
            acc.y = fmaf(a[r1], h.y, acc.y);
            acc.z = fmaf(a[r1], h.z, acc.z);
            acc.w = fmaf(a[r1], h.w, acc.w);
        }

        ((float4*)(out + (size_t)(base + i) * 128))[lane] = acc;

        // Prefetch i+2 into stage (i+2)%3 (stage read at i-1, already consumed).
        if (i + 2 < IPW) {
            __syncwarp();
            issue(i + 2, (i + 2) % 3);
        }
    }
}

// Inputs (metadata order): indices, core0, core1, core2
extern "C" void kernel_launch(void* const* d_in, const int* in_sizes, int n_in,
                              void* d_out, int out_size)
{
    const void*  indices = d_in[0];
    const float* core0   = (const float*)d_in[1];
    const float* core1   = (const float*)d_in[2];
    const float* core2   = (const float*)d_in[3];
    float* out = (float*)d_out;

    tt_build_H<<<NPAIRS / 8, 256>>>(core1, core2);
    tt_gather<<<GBLOCKS, 256>>>(indices, core0, out);
}